// round 7
// baseline (speedup 1.0000x reference)
#include <cuda_runtime.h>
#include <cuda_bf16.h>

#define N_ 16
#define C_ 64
#define H_ 64
#define W_ 64

typedef __nv_bfloat16 bf16;

// ---- static device scratch (allocation-free) ------------------------------
__device__ __align__(16) float g_t4[N_ * C_ * H_ * W_];          // 16 MB
// transposed/split weights: [tap(49)][chunk(4)][co(64)][32 halves interleaved]
// 32-halve vector = 4 c-blocks of 8: [hi2c,hi2c+1,hi2c+8,hi2c+9,lo2c,lo2c+1,lo2c+8,lo2c+9]
__device__ __align__(16) bf16  g_wt[49 * 4 * 64 * 32];           // 784 KB

// ---- helpers --------------------------------------------------------------
__device__ __forceinline__ void cp_async16(unsigned dst, const void* src) {
    asm volatile("cp.async.cg.shared.global [%0], [%1], 16;" :: "r"(dst), "l"(src));
}
__device__ __forceinline__ void cp_commit() {
    asm volatile("cp.async.commit_group;");
}
template <int N>
__device__ __forceinline__ void cp_wait() {
    asm volatile("cp.async.wait_group %0;" :: "n"(N));
}

#define MMA_BF16(D, a0,a1,a2,a3, b0,b1)                                       \
    asm volatile("mma.sync.aligned.m16n8k16.row.col.f32.bf16.bf16.f32 "       \
        "{%0,%1,%2,%3}, {%4,%5,%6,%7}, {%8,%9}, {%0,%1,%2,%3};"               \
        : "+f"(D[0]), "+f"(D[1]), "+f"(D[2]), "+f"(D[3])                      \
        : "r"(a0), "r"(a1), "r"(a2), "r"(a3), "r"(b0), "r"(b1))

// position of hi-element k (0..15) inside the 32-halve interleaved vector
__device__ __forceinline__ int frag_pos(int k) {
    return (k < 8) ? ((k >> 1) * 8 + (k & 1))
                   : (((k & 7) >> 1) * 8 + 2 + (k & 1));
}

// ---------------------------------------------------------------------------
// Weight transpose/split/negate into interleaved fragment layout.
// ---------------------------------------------------------------------------
__global__ void wtrans_kernel(const float* __restrict__ w4)
{
    int idx = blockIdx.x * 256 + threadIdx.x;
    if (idx >= 49 * 4 * 64 * 16) return;
    int cl    = idx & 15;
    int co    = (idx >> 4) & 63;
    int chunk = (idx >> 10) & 3;
    int tap   = idx >> 12;
    float v = -w4[co * 3136 + (chunk * 16 + cl) * 49 + tap];
    bf16 hi = __float2bfloat16(v);
    bf16 lo = __float2bfloat16(v - __bfloat162float(hi));
    bf16* t = g_wt + (size_t)(tap * 4 + chunk) * 2048;   // 64*32
    int p = frag_pos(cl);
    t[co * 32 + p]     = hi;
    t[co * 32 + p + 4] = lo;
}

// ---------------------------------------------------------------------------
// Conv 7x7 via bf16 tensor cores (split-precision implicit GEMM).
// Block: 256 thr, out tile co64 x (1 row x 64 w) of one n. Grid (64, 16).
// SMEM: halo[7 rows][70 px][32 halves] (31.4KB) + 3 weight bufs (12KB).
// All fragment loads are single LDS.128, conflict-free (64B pixel stride).
// ---------------------------------------------------------------------------
#define HALO_HALVES (7 * 70 * 32)      // 15680
#define SWT_HALVES  (64 * 32)          // 2048 per buffer

__global__ __launch_bounds__(256)
void conv7x7_mma_kernel(const float* __restrict__ x)
{
    __shared__ __align__(16) bf16 halo[HALO_HALVES];
    __shared__ __align__(16) bf16 swt[3 * SWT_HALVES];

    const int tid    = threadIdx.x;
    const int warp   = tid >> 5;
    const int lane   = tid & 31;
    const int warp_m = warp >> 1;     // 0..3 : co slice of 16
    const int warp_h = warp & 1;      // 0..1 : w half (0..31 / 32..63)
    const int g      = lane >> 2;     // 0..7
    const int c      = lane & 3;      // 0..3

    const int n  = blockIdx.y;
    const int h0 = blockIdx.x;        // one output row per block

    float d[4][4];
    #pragma unroll
    for (int j = 0; j < 4; j++)
        #pragma unroll
        for (int k = 0; k < 4; k++) d[j][k] = 0.0f;

    const unsigned swt_base = (unsigned)__cvta_generic_to_shared(swt);
    const int co_w = tid >> 2, ch_w = tid & 3;   // cp.async tiling

    for (int chunk = 0; chunk < 4; chunk++) {
        __syncthreads();   // previous chunk readers done before halo overwrite

        // ---- zero halo ----
        float4* hz = (float4*)halo;
        for (int i = tid; i < HALO_HALVES / 8; i += 256)
            hz[i] = make_float4(0.f, 0.f, 0.f, 0.f);
        __syncthreads();

        // ---- fill halo: rows h0-3 .. h0+3, interleaved bf16 hi/lo ----
        for (int i = tid; i < 7 * 64 * 16; i += 256) {
            int w  = i & 63;
            int cl = (i >> 6) & 15;
            int r  = i >> 10;              // 0..6
            int gh = h0 - 3 + r;
            if ((unsigned)gh < (unsigned)H_) {
                float v = x[((n * C_ + chunk * 16 + cl) * H_ + gh) * W_ + w];
                bf16 hi = __float2bfloat16(v);
                bf16 lo = __float2bfloat16(v - __bfloat162float(hi));
                int base = (r * 70 + w + 3) * 32;
                int p = frag_pos(cl);
                halo[base + p]     = hi;
                halo[base + p + 4] = lo;
            }
        }

        // ---- prefetch weights: taps 0 and 1 ----
        {
            const char* s0 = (const char*)(g_wt + (size_t)(0 * 4 + chunk) * 2048);
            cp_async16(swt_base + (unsigned)(co_w * 64 + ch_w * 16),
                       s0 + co_w * 64 + ch_w * 16);
            cp_commit();
            const char* s1 = (const char*)(g_wt + (size_t)(1 * 4 + chunk) * 2048);
            cp_async16(swt_base + (unsigned)(4096 + co_w * 64 + ch_w * 16),
                       s1 + co_w * 64 + ch_w * 16);
            cp_commit();
        }

        int kh = 0, kw = 0;
        for (int tap = 0; tap < 49; tap++) {
            const int buf = tap - (tap / 3) * 3;     // tap % 3

            // wait: current tap's buffer complete (per-thread)
            if (tap < 47)      cp_wait<1>();
            else if (tap == 47) cp_wait<1>();
            else                cp_wait<0>();

            __syncthreads();   // visibility of buf[tap] + all warps done with tap-1

            // prefetch tap+2 into buf (tap+2)%3 == (tap-1)%3 (just proven drained)
            if (tap + 2 <= 48) {
                const char* src = (const char*)(g_wt + (size_t)((tap + 2) * 4 + chunk) * 2048);
                cp_async16(swt_base + (unsigned)(((tap + 2) - ((tap + 2) / 3) * 3) * 4096
                                                 + co_w * 64 + ch_w * 16),
                           src + co_w * 64 + ch_w * 16);
                cp_commit();
            }

            // ---- A fragments: 2x LDS.128 ----
            const bf16* wb = swt + buf * SWT_HALVES;
            const int coA = warp_m * 16 + g;
            uint4 A0 = *(const uint4*)(wb + coA * 32 + c * 8);        // a0,a2,al0,al2
            uint4 A1 = *(const uint4*)(wb + (coA + 8) * 32 + c * 8);  // a1,a3,al1,al3

            // ---- B fragments: 1x LDS.128 per j + 3 split MMAs ----
            const bf16* hb = halo + (kh * 70 + warp_h * 32 + g + kw) * 32 + c * 8;
            #pragma unroll
            for (int j = 0; j < 4; j++) {
                uint4 B = *(const uint4*)(hb + j * (8 * 32));          // bh0,bh1,bl0,bl1
                MMA_BF16(d[j], A0.x, A1.x, A0.y, A1.y, B.x, B.y);      // whi*xhi
                MMA_BF16(d[j], A0.x, A1.x, A0.y, A1.y, B.z, B.w);      // whi*xlo
                MMA_BF16(d[j], A0.z, A1.z, A0.w, A1.w, B.x, B.y);      // wlo*xhi
            }

            if (++kw == 7) { kw = 0; ++kh; }
        }
    }

    // ---- store t4 tile ----
    #pragma unroll
    for (int j = 0; j < 4; j++) {
        int wcol = warp_h * 32 + j * 8 + 2 * c;
        #pragma unroll
        for (int s = 0; s < 2; s++) {
            int co = warp_m * 16 + g + s * 8;
            float2 v = make_float2(d[j][s * 2], d[j][s * 2 + 1]);
            *(float2*)&g_t4[((n * C_ + co) * H_ + h0) * W_ + wcol] = v;
        }
    }
}

// ---------------------------------------------------------------------------
// Kernel 2 (unchanged): out = x * depthwise(t4) + w8 @ roll(x,1,H)
// ---------------------------------------------------------------------------
typedef unsigned long long ull_t;
__device__ __forceinline__ void ffma2(ull_t& d, ull_t a, ull_t b) {
    asm("fma.rn.f32x2 %0, %1, %2, %0;" : "+l"(d) : "l"(a), "l"(b));
}
__device__ __forceinline__ ull_t bcast2(float v) {
    ull_t r; asm("mov.b64 %0, {%1, %1};" : "=l"(r) : "f"(v)); return r;
}
__device__ __forceinline__ void unpack2(ull_t v, float& lo, float& hi) {
    asm("mov.b64 {%0, %1}, %2;" : "=f"(lo), "=f"(hi) : "l"(v));
}

#define SW8S 66

__global__ __launch_bounds__(256)
void fuse_kernel(const float* __restrict__ x, const float* __restrict__ w5,
                 const float* __restrict__ w8, float* __restrict__ out)
{
    __shared__ __align__(16) float sxr[64 * 64];
    __shared__ __align__(16) float sw8t[64 * SW8S];

    const int h  = blockIdx.x;
    const int n  = blockIdx.y;
    const int hr = (h + H_ - 1) & (H_ - 1);
    const int tid = threadIdx.x;

    const float* xn = x + n * (C_ * H_ * W_);

    for (int idx = tid; idx < 64 * 64; idx += 256) {
        int ci = idx >> 6, w = idx & 63;
        sxr[idx] = xn[ci * (H_ * W_) + hr * W_ + w];
    }
    for (int idx = tid; idx < 64 * 64; idx += 256) {
        int co = idx >> 6, ci = idx & 63;
        sw8t[ci * SW8S + co] = w8[co * 64 + ci];
    }
    __syncthreads();

    const int warp = tid >> 5;
    const int lane = tid & 31;
    const int co0  = warp * 8;

    ull_t acc2[4][2];
    #pragma unroll
    for (int j2 = 0; j2 < 4; j2++) { acc2[j2][0] = 0ULL; acc2[j2][1] = 0ULL; }

    #pragma unroll 4
    for (int ci = 0; ci < 64; ci++) {
        ull_t xpa = bcast2(sxr[ci * 64 + lane]);
        ull_t xpb = bcast2(sxr[ci * 64 + lane + 32]);
        const ull_t* wp = (const ull_t*)&sw8t[ci * SW8S + co0];
        #pragma unroll
        for (int j2 = 0; j2 < 4; j2++) {
            ull_t w2 = wp[j2];
            ffma2(acc2[j2][0], w2, xpa);
            ffma2(acc2[j2][1], w2, xpb);
        }
    }

    #pragma unroll
    for (int j2 = 0; j2 < 4; j2++) {
        #pragma unroll
        for (int v = 0; v < 2; v++) {
            const int w = lane + 32 * v;
            float tlo, thi;
            unpack2(acc2[j2][v], tlo, thi);
            float tacc[2] = { tlo, thi };
            #pragma unroll
            for (int s = 0; s < 2; s++) {
                const int co = co0 + 2 * j2 + s;
                const float* t4row = g_t4 + ((n * C_ + co) * H_ + h) * W_;
                const float* xrow  = xn + co * (H_ * W_) + h * W_;
                float*       orow  = out + ((size_t)((n * C_ + co) * H_ + h)) * W_;
                const float a0 = w5[co * 3 + 0];
                const float a1 = w5[co * 3 + 1];
                const float a2 = w5[co * 3 + 2];
                float tm = (w >= 2)      ? t4row[w - 2] : 0.0f;
                float tc = t4row[w];
                float tp = (w < W_ - 2)  ? t4row[w + 2] : 0.0f;
                float t5 = a0 * tm + a1 * tc + a2 * tp;
                orow[w] = xrow[w] * t5 + tacc[s];
            }
        }
    }
}

// ---------------------------------------------------------------------------
extern "C" void kernel_launch(void* const* d_in, const int* in_sizes, int n_in,
                              void* d_out, int out_size)
{
    const float* x  = (const float*)d_in[0];   // (16,64,64,64)
    const float* w4 = (const float*)d_in[1];   // (64,64,7,7)
    const float* w5 = (const float*)d_in[2];   // (64,1,1,3)
    const float* w8 = (const float*)d_in[3];   // (64,64,1,1)
    float* out = (float*)d_out;

    wtrans_kernel<<<784, 256>>>(w4);

    dim3 g1(H_, N_);                 // (64, 16)
    conv7x7_mma_kernel<<<g1, 256>>>(x);

    dim3 g2(H_, N_);                 // (64, 16)
    fuse_kernel<<<g2, 256>>>(x, w5, w8, out);
}

// round 9
// speedup vs baseline: 1.9710x; 1.9710x over previous
#include <cuda_runtime.h>
#include <cuda_fp16.h>

#define N_ 16
#define C_ 64
#define H_ 64
#define W_ 64

// ---- static device scratch (allocation-free) ------------------------------
__device__ __align__(16) float g_t4[N_ * C_ * H_ * W_];          // 16 MB
// fp16 weights: [tap(49)][chunk(2)][co(64)][32 halves interleaved], negated
__device__ __align__(16) __half g_wt16[49 * 2 * 64 * 32];        // 401 KB

// ---- helpers --------------------------------------------------------------
__device__ __forceinline__ void cp_async16(unsigned dst, const void* src) {
    asm volatile("cp.async.cg.shared.global [%0], [%1], 16;" :: "r"(dst), "l"(src));
}
__device__ __forceinline__ void cp_commit() {
    asm volatile("cp.async.commit_group;");
}
template <int N>
__device__ __forceinline__ void cp_wait() {
    asm volatile("cp.async.wait_group %0;" :: "n"(N));
}

#define MMA_F16(D, a0,a1,a2,a3, b0,b1)                                        \
    asm volatile("mma.sync.aligned.m16n8k16.row.col.f32.f16.f16.f32 "         \
        "{%0,%1,%2,%3}, {%4,%5,%6,%7}, {%8,%9}, {%0,%1,%2,%3};"               \
        : "+f"(D[0]), "+f"(D[1]), "+f"(D[2]), "+f"(D[3])                      \
        : "r"(a0), "r"(a1), "r"(a2), "r"(a3), "r"(b0), "r"(b1))

// interleave position of k (0..31) inside a 32-halve row:
// step s = k/16, kk = k%16; c-block of 4: [2c,2c+1,2c+8,2c+9]; p = 8c+4s+sub
__device__ __forceinline__ int frag_pos32(int k) {
    int s  = k >> 4;
    int kk = k & 15;
    int c  = (kk & 7) >> 1;
    int sub = (kk < 8) ? (kk & 1) : (2 | (kk & 1));
    return 8 * c + 4 * s + sub;
}

// ---------------------------------------------------------------------------
// Weight transpose/negate into interleaved fp16 fragment layout.
// ---------------------------------------------------------------------------
__global__ void wtrans_kernel(const float* __restrict__ w4)
{
    int idx = blockIdx.x * 256 + threadIdx.x;
    if (idx >= 49 * 2 * 64 * 32) return;
    int k     = idx & 31;
    int co    = (idx >> 5) & 63;
    int chunk = (idx >> 11) & 1;
    int tap   = idx >> 12;
    int ci    = chunk * 32 + k;
    float v = -w4[co * 3136 + ci * 49 + tap];
    g_wt16[(size_t)((tap * 2 + chunk) * 64 + co) * 32 + frag_pos32(k)] = __float2half(v);
}

// ---------------------------------------------------------------------------
// Conv 7x7 via fp16 tensor cores (single GEMM, fp32 accum).
// Block: 256 thr, out tile co64 x (1 row x 64 w) of one n. Grid (64, 16).
// SMEM: halo[7 rows][70 px][32 halves] (31.4KB) + 2 weight bufs (8KB).
// ---------------------------------------------------------------------------
#define HALO_HALVES (7 * 70 * 32)      // 15680
#define SWT_HALVES  (64 * 32)          // 2048 per buffer

__global__ __launch_bounds__(256)
void conv7x7_mma_kernel(const float* __restrict__ x)
{
    __shared__ __align__(16) __half halo[HALO_HALVES];
    __shared__ __align__(16) __half swt[2 * SWT_HALVES];

    const int tid    = threadIdx.x;
    const int warp   = tid >> 5;
    const int lane   = tid & 31;
    const int warp_m = warp >> 1;     // 0..3 : co slice of 16
    const int warp_h = warp & 1;      // 0..1 : w half
    const int g      = lane >> 2;     // 0..7
    const int c      = lane & 3;      // 0..3

    const int n  = blockIdx.y;
    const int h0 = blockIdx.x;        // one output row per block

    float d[4][4];
    #pragma unroll
    for (int j = 0; j < 4; j++)
        #pragma unroll
        for (int k = 0; k < 4; k++) d[j][k] = 0.0f;

    const unsigned swt_base = (unsigned)__cvta_generic_to_shared(swt);
    const int co_w = tid >> 2, ch_w = tid & 3;   // cp.async tiling (64B rows)

    for (int chunk = 0; chunk < 2; chunk++) {
        __syncthreads();   // previous chunk readers done before halo overwrite

        // ---- zero halo ----
        float4* hz = (float4*)halo;
        for (int i = tid; i < HALO_HALVES / 8; i += 256)
            hz[i] = make_float4(0.f, 0.f, 0.f, 0.f);
        __syncthreads();

        // ---- fill halo: rows h0-3 .. h0+3, interleaved fp16 ----
        for (int i = tid; i < 7 * 64 * 32; i += 256) {
            int w  = i & 63;
            int cl = (i >> 6) & 31;
            int r  = i >> 11;              // 0..6
            int gh = h0 - 3 + r;
            if ((unsigned)gh < (unsigned)H_) {
                float v = x[((n * C_ + chunk * 32 + cl) * H_ + gh) * W_ + w];
                halo[(r * 70 + w + 3) * 32 + frag_pos32(cl)] = __float2half(v);
            }
        }

        // ---- prefetch weights for tap 0 into buf 0 ----
        {
            const char* src = (const char*)(g_wt16 + (size_t)((0 * 2 + chunk) * 64) * 32);
            cp_async16(swt_base + (unsigned)(co_w * 64 + ch_w * 16),
                       src + co_w * 64 + ch_w * 16);
            cp_commit();
        }
        __syncthreads();   // halo visible

        int kh = 0, kw = 0;
        for (int tap = 0; tap < 49; tap++) {
            const int buf = tap & 1;

            if (tap < 48) {
                const char* src = (const char*)(g_wt16 + (size_t)(((tap + 1) * 2 + chunk) * 64) * 32);
                cp_async16(swt_base + (unsigned)((buf ^ 1) * SWT_HALVES * 2 + co_w * 64 + ch_w * 16),
                           src + co_w * 64 + ch_w * 16);
                cp_commit();
                cp_wait<1>();
            } else {
                cp_wait<0>();
            }
            __syncthreads();   // current weight buffer visible to all warps

            // ---- A fragments: 2x LDS.128 (both k-steps) ----
            const __half* wb = swt + buf * SWT_HALVES;
            const int coA = warp_m * 16 + g;
            uint4 A0 = *(const uint4*)(wb + coA * 32 + c * 8);
            uint4 A1 = *(const uint4*)(wb + (coA + 8) * 32 + c * 8);

            // ---- B fragments: 1x LDS.128 per n-tile (both k-steps) ----
            const __half* hb = halo + (kh * 70 + warp_h * 32 + g + kw) * 32 + c * 8;
            #pragma unroll
            for (int j = 0; j < 4; j++) {
                uint4 B = *(const uint4*)(hb + j * (8 * 32));
                MMA_F16(d[j], A0.x, A1.x, A0.y, A1.y, B.x, B.y);   // k-step 0
                MMA_F16(d[j], A0.z, A1.z, A0.w, A1.w, B.z, B.w);   // k-step 1
            }
            __syncthreads();   // all warps done with buf before it is overwritten

            if (++kw == 7) { kw = 0; ++kh; }
        }
    }

    // ---- store t4 tile ----
    #pragma unroll
    for (int j = 0; j < 4; j++) {
        int wcol = warp_h * 32 + j * 8 + 2 * c;
        #pragma unroll
        for (int s = 0; s < 2; s++) {
            int co = warp_m * 16 + g + s * 8;
            float2 v = make_float2(d[j][s * 2], d[j][s * 2 + 1]);
            *(float2*)&g_t4[((n * C_ + co) * H_ + h0) * W_ + wcol] = v;
        }
    }
}

// ---------------------------------------------------------------------------
// Kernel 2 (unchanged): out = x * depthwise(t4) + w8 @ roll(x,1,H)
// ---------------------------------------------------------------------------
typedef unsigned long long ull_t;
__device__ __forceinline__ void ffma2(ull_t& d, ull_t a, ull_t b) {
    asm("fma.rn.f32x2 %0, %1, %2, %0;" : "+l"(d) : "l"(a), "l"(b));
}
__device__ __forceinline__ ull_t bcast2(float v) {
    ull_t r; asm("mov.b64 %0, {%1, %1};" : "=l"(r) : "f"(v)); return r;
}
__device__ __forceinline__ void unpack2(ull_t v, float& lo, float& hi) {
    asm("mov.b64 {%0, %1}, %2;" : "=f"(lo), "=f"(hi) : "l"(v));
}

#define SW8S 66

__global__ __launch_bounds__(256)
void fuse_kernel(const float* __restrict__ x, const float* __restrict__ w5,
                 const float* __restrict__ w8, float* __restrict__ out)
{
    __shared__ __align__(16) float sxr[64 * 64];
    __shared__ __align__(16) float sw8t[64 * SW8S];

    const int h  = blockIdx.x;
    const int n  = blockIdx.y;
    const int hr = (h + H_ - 1) & (H_ - 1);
    const int tid = threadIdx.x;

    const float* xn = x + n * (C_ * H_ * W_);

    for (int idx = tid; idx < 64 * 64; idx += 256) {
        int ci = idx >> 6, w = idx & 63;
        sxr[idx] = xn[ci * (H_ * W_) + hr * W_ + w];
    }
    for (int idx = tid; idx < 64 * 64; idx += 256) {
        int co = idx >> 6, ci = idx & 63;
        sw8t[ci * SW8S + co] = w8[co * 64 + ci];
    }
    __syncthreads();

    const int warp = tid >> 5;
    const int lane = tid & 31;
    const int co0  = warp * 8;

    ull_t acc2[4][2];
    #pragma unroll
    for (int j2 = 0; j2 < 4; j2++) { acc2[j2][0] = 0ULL; acc2[j2][1] = 0ULL; }

    #pragma unroll 4
    for (int ci = 0; ci < 64; ci++) {
        ull_t xpa = bcast2(sxr[ci * 64 + lane]);
        ull_t xpb = bcast2(sxr[ci * 64 + lane + 32]);
        const ull_t* wp = (const ull_t*)&sw8t[ci * SW8S + co0];
        #pragma unroll
        for (int j2 = 0; j2 < 4; j2++) {
            ull_t w2 = wp[j2];
            ffma2(acc2[j2][0], w2, xpa);
            ffma2(acc2[j2][1], w2, xpb);
        }
    }

    #pragma unroll
    for (int j2 = 0; j2 < 4; j2++) {
        #pragma unroll
        for (int v = 0; v < 2; v++) {
            const int w = lane + 32 * v;
            float tlo, thi;
            unpack2(acc2[j2][v], tlo, thi);
            float tacc[2] = { tlo, thi };
            #pragma unroll
            for (int s = 0; s < 2; s++) {
                const int co = co0 + 2 * j2 + s;
                const float* t4row = g_t4 + ((n * C_ + co) * H_ + h) * W_;
                const float* xrow  = xn + co * (H_ * W_) + h * W_;
                float*       orow  = out + ((size_t)((n * C_ + co) * H_ + h)) * W_;
                const float a0 = w5[co * 3 + 0];
                const float a1 = w5[co * 3 + 1];
                const float a2 = w5[co * 3 + 2];
                float tm = (w >= 2)      ? t4row[w - 2] : 0.0f;
                float tc = t4row[w];
                float tp = (w < W_ - 2)  ? t4row[w + 2] : 0.0f;
                float t5 = a0 * tm + a1 * tc + a2 * tp;
                orow[w] = xrow[w] * t5 + tacc[s];
            }
        }
    }
}

// ---------------------------------------------------------------------------
extern "C" void kernel_launch(void* const* d_in, const int* in_sizes, int n_in,
                              void* d_out, int out_size)
{
    const float* x  = (const float*)d_in[0];   // (16,64,64,64)
    const float* w4 = (const float*)d_in[1];   // (64,64,7,7)
    const float* w5 = (const float*)d_in[2];   // (64,1,1,3)
    const float* w8 = (const float*)d_in[3];   // (64,64,1,1)
    float* out = (float*)d_out;

    wtrans_kernel<<<784, 256>>>(w4);

    dim3 g1(H_, N_);                 // (64, 16)
    conv7x7_mma_kernel<<<g1, 256>>>(x);

    dim3 g2(H_, N_);                 // (64, 16)
    fuse_kernel<<<g2, 256>>>(x, w5, w8, out);
}

// round 10
// speedup vs baseline: 2.2299x; 1.1314x over previous
#include <cuda_runtime.h>
#include <cuda_fp16.h>

#define N_ 16
#define C_ 64
#define H_ 64
#define W_ 64

// ---- static device scratch (allocation-free) ------------------------------
__device__ __align__(16) float g_t4[N_ * C_ * H_ * W_];          // 16 MB
// fp16 weights: [tap(49)][chunk(2)][co(64)][32 halves interleaved], negated
__device__ __align__(16) __half g_wt16[49 * 2 * 64 * 32];        // 401 KB

// ---- helpers --------------------------------------------------------------
__device__ __forceinline__ void cp_async16(unsigned dst, const void* src) {
    asm volatile("cp.async.cg.shared.global [%0], [%1], 16;" :: "r"(dst), "l"(src));
}
__device__ __forceinline__ void cp_commit() {
    asm volatile("cp.async.commit_group;");
}
template <int N>
__device__ __forceinline__ void cp_wait() {
    asm volatile("cp.async.wait_group %0;" :: "n"(N));
}

#define MMA_F16(D, a0,a1,a2,a3, b0,b1)                                        \
    asm volatile("mma.sync.aligned.m16n8k16.row.col.f32.f16.f16.f32 "         \
        "{%0,%1,%2,%3}, {%4,%5,%6,%7}, {%8,%9}, {%0,%1,%2,%3};"               \
        : "+f"(D[0]), "+f"(D[1]), "+f"(D[2]), "+f"(D[3])                      \
        : "r"(a0), "r"(a1), "r"(a2), "r"(a3), "r"(b0), "r"(b1))

// interleave position of k (0..31) inside a 32-halve row:
// step s = k/16, kk = k%16; c-block of 4: [2c,2c+1,2c+8,2c+9]; p = 8c+4s+sub
__device__ __forceinline__ int frag_pos32(int k) {
    int s  = k >> 4;
    int kk = k & 15;
    int c  = (kk & 7) >> 1;
    int sub = (kk < 8) ? (kk & 1) : (2 | (kk & 1));
    return 8 * c + 4 * s + sub;
}

// ---------------------------------------------------------------------------
// Weight transpose/negate into interleaved fp16 fragment layout.
// ---------------------------------------------------------------------------
__global__ void wtrans_kernel(const float* __restrict__ w4)
{
    int idx = blockIdx.x * 256 + threadIdx.x;
    if (idx >= 49 * 2 * 64 * 32) return;
    int k     = idx & 31;
    int co    = (idx >> 5) & 63;
    int chunk = (idx >> 11) & 1;
    int tap   = idx >> 12;
    int ci    = chunk * 32 + k;
    float v = -w4[co * 3136 + ci * 49 + tap];
    g_wt16[(size_t)((tap * 2 + chunk) * 64 + co) * 32 + frag_pos32(k)] = __float2half(v);
}

// ---------------------------------------------------------------------------
// Conv 7x7 via fp16 tensor cores (single GEMM, fp32 accum).
// Block: 256 thr, out tile co64 x (2 rows x 64 w) of one n. Grid (32, 16).
// Warp: warp_m = co slice of 16, warp_r = output row. 16 MMAs per tap per warp.
// SMEM: halo[8 rows][70 px][32 halves] (35.8KB) + 2 weight bufs (8KB) = 44KB.
// ---------------------------------------------------------------------------
#define HALO_HALVES (8 * 70 * 32)      // 17920
#define SWT_HALVES  (64 * 32)          // 2048 per buffer

__global__ __launch_bounds__(256)
void conv7x7_mma_kernel(const float* __restrict__ x)
{
    __shared__ __align__(16) __half halo[HALO_HALVES];
    __shared__ __align__(16) __half swt[2 * SWT_HALVES];

    const int tid    = threadIdx.x;
    const int warp   = tid >> 5;
    const int lane   = tid & 31;
    const int warp_m = warp >> 1;     // 0..3 : co slice of 16
    const int warp_r = warp & 1;      // 0..1 : output row within tile
    const int g      = lane >> 2;     // 0..7
    const int c      = lane & 3;      // 0..3

    const int n  = blockIdx.y;
    const int h0 = blockIdx.x * 2;    // two output rows per block

    float d[8][4];
    #pragma unroll
    for (int j = 0; j < 8; j++)
        #pragma unroll
        for (int k = 0; k < 4; k++) d[j][k] = 0.0f;

    const unsigned swt_base = (unsigned)__cvta_generic_to_shared(swt);
    const int co_w = tid >> 2, ch_w = tid & 3;   // cp.async tiling (64B rows)

    for (int chunk = 0; chunk < 2; chunk++) {
        __syncthreads();   // previous chunk readers done before halo overwrite

        // ---- zero halo ----
        float4* hz = (float4*)halo;
        for (int i = tid; i < HALO_HALVES / 8; i += 256)
            hz[i] = make_float4(0.f, 0.f, 0.f, 0.f);
        __syncthreads();

        // ---- fill halo: rows h0-3 .. h0+4, interleaved fp16 ----
        for (int i = tid; i < 8 * 64 * 32; i += 256) {
            int w  = i & 63;
            int cl = (i >> 6) & 31;
            int r  = i >> 11;              // 0..7
            int gh = h0 - 3 + r;
            if ((unsigned)gh < (unsigned)H_) {
                float v = x[((n * C_ + chunk * 32 + cl) * H_ + gh) * W_ + w];
                halo[(r * 70 + w + 3) * 32 + frag_pos32(cl)] = __float2half(v);
            }
        }

        // ---- prefetch weights for tap 0 into buf 0 ----
        {
            const char* src = (const char*)(g_wt16 + (size_t)((0 * 2 + chunk) * 64) * 32);
            cp_async16(swt_base + (unsigned)(co_w * 64 + ch_w * 16),
                       src + co_w * 64 + ch_w * 16);
            cp_commit();
        }
        __syncthreads();   // halo visible

        int kh = 0, kw = 0;
        for (int tap = 0; tap < 49; tap++) {
            const int buf = tap & 1;

            if (tap < 48) {
                const char* src = (const char*)(g_wt16 + (size_t)(((tap + 1) * 2 + chunk) * 64) * 32);
                cp_async16(swt_base + (unsigned)((buf ^ 1) * SWT_HALVES * 2 + co_w * 64 + ch_w * 16),
                           src + co_w * 64 + ch_w * 16);
                cp_commit();
                cp_wait<1>();
            } else {
                cp_wait<0>();
            }
            __syncthreads();   // current weight buffer visible to all warps

            // ---- A fragments: 2x LDS.128 (both k-steps) ----
            const __half* wb = swt + buf * SWT_HALVES;
            const int coA = warp_m * 16 + g;
            uint4 A0 = *(const uint4*)(wb + coA * 32 + c * 8);
            uint4 A1 = *(const uint4*)(wb + (coA + 8) * 32 + c * 8);

            // ---- B fragments: full 64-px row, 8 n-tiles, 2 MMAs each ----
            const __half* hb = halo + ((kh + warp_r) * 70 + g + kw) * 32 + c * 8;
            #pragma unroll
            for (int j = 0; j < 8; j++) {
                uint4 B = *(const uint4*)(hb + j * (8 * 32));
                MMA_F16(d[j], A0.x, A1.x, A0.y, A1.y, B.x, B.y);   // k-step 0
                MMA_F16(d[j], A0.z, A1.z, A0.w, A1.w, B.z, B.w);   // k-step 1
            }
            __syncthreads();   // all warps done with buf before it is overwritten

            if (++kw == 7) { kw = 0; ++kh; }
        }
    }

    // ---- store t4 tile (row h0 + warp_r, full 64 px) ----
    const int hrow = h0 + warp_r;
    #pragma unroll
    for (int j = 0; j < 8; j++) {
        int wcol = j * 8 + 2 * c;
        #pragma unroll
        for (int s = 0; s < 2; s++) {
            int co = warp_m * 16 + g + s * 8;
            float2 v = make_float2(d[j][s * 2], d[j][s * 2 + 1]);
            *(float2*)&g_t4[((n * C_ + co) * H_ + hrow) * W_ + wcol] = v;
        }
    }
}

// ---------------------------------------------------------------------------
// Kernel 2 (unchanged): out = x * depthwise(t4) + w8 @ roll(x,1,H)
// ---------------------------------------------------------------------------
typedef unsigned long long ull_t;
__device__ __forceinline__ void ffma2(ull_t& d, ull_t a, ull_t b) {
    asm("fma.rn.f32x2 %0, %1, %2, %0;" : "+l"(d) : "l"(a), "l"(b));
}
__device__ __forceinline__ ull_t bcast2(float v) {
    ull_t r; asm("mov.b64 %0, {%1, %1};" : "=l"(r) : "f"(v)); return r;
}
__device__ __forceinline__ void unpack2(ull_t v, float& lo, float& hi) {
    asm("mov.b64 {%0, %1}, %2;" : "=f"(lo), "=f"(hi) : "l"(v));
}

#define SW8S 66

__global__ __launch_bounds__(256)
void fuse_kernel(const float* __restrict__ x, const float* __restrict__ w5,
                 const float* __restrict__ w8, float* __restrict__ out)
{
    __shared__ __align__(16) float sxr[64 * 64];
    __shared__ __align__(16) float sw8t[64 * SW8S];

    const int h  = blockIdx.x;
    const int n  = blockIdx.y;
    const int hr = (h + H_ - 1) & (H_ - 1);
    const int tid = threadIdx.x;

    const float* xn = x + n * (C_ * H_ * W_);

    for (int idx = tid; idx < 64 * 64; idx += 256) {
        int ci = idx >> 6, w = idx & 63;
        sxr[idx] = xn[ci * (H_ * W_) + hr * W_ + w];
    }
    for (int idx = tid; idx < 64 * 64; idx += 256) {
        int co = idx >> 6, ci = idx & 63;
        sw8t[ci * SW8S + co] = w8[co * 64 + ci];
    }
    __syncthreads();

    const int warp = tid >> 5;
    const int lane = tid & 31;
    const int co0  = warp * 8;

    ull_t acc2[4][2];
    #pragma unroll
    for (int j2 = 0; j2 < 4; j2++) { acc2[j2][0] = 0ULL; acc2[j2][1] = 0ULL; }

    #pragma unroll 4
    for (int ci = 0; ci < 64; ci++) {
        ull_t xpa = bcast2(sxr[ci * 64 + lane]);
        ull_t xpb = bcast2(sxr[ci * 64 + lane + 32]);
        const ull_t* wp = (const ull_t*)&sw8t[ci * SW8S + co0];
        #pragma unroll
        for (int j2 = 0; j2 < 4; j2++) {
            ull_t w2 = wp[j2];
            ffma2(acc2[j2][0], w2, xpa);
            ffma2(acc2[j2][1], w2, xpb);
        }
    }

    #pragma unroll
    for (int j2 = 0; j2 < 4; j2++) {
        #pragma unroll
        for (int v = 0; v < 2; v++) {
            const int w = lane + 32 * v;
            float tlo, thi;
            unpack2(acc2[j2][v], tlo, thi);
            float tacc[2] = { tlo, thi };
            #pragma unroll
            for (int s = 0; s < 2; s++) {
                const int co = co0 + 2 * j2 + s;
                const float* t4row = g_t4 + ((n * C_ + co) * H_ + h) * W_;
                const float* xrow  = xn + co * (H_ * W_) + h * W_;
                float*       orow  = out + ((size_t)((n * C_ + co) * H_ + h)) * W_;
                const float a0 = w5[co * 3 + 0];
                const float a1 = w5[co * 3 + 1];
                const float a2 = w5[co * 3 + 2];
                float tm = (w >= 2)      ? t4row[w - 2] : 0.0f;
                float tc = t4row[w];
                float tp = (w < W_ - 2)  ? t4row[w + 2] : 0.0f;
                float t5 = a0 * tm + a1 * tc + a2 * tp;
                orow[w] = xrow[w] * t5 + tacc[s];
            }
        }
    }
}

// ---------------------------------------------------------------------------
extern "C" void kernel_launch(void* const* d_in, const int* in_sizes, int n_in,
                              void* d_out, int out_size)
{
    const float* x  = (const float*)d_in[0];   // (16,64,64,64)
    const float* w4 = (const float*)d_in[1];   // (64,64,7,7)
    const float* w5 = (const float*)d_in[2];   // (64,1,1,3)
    const float* w8 = (const float*)d_in[3];   // (64,64,1,1)
    float* out = (float*)d_out;

    wtrans_kernel<<<784, 256>>>(w4);

    dim3 g1(H_ / 2, N_);             // (32, 16)
    conv7x7_mma_kernel<<<g1, 256>>>(x);

    dim3 g2(H_, N_);                 // (64, 16)
    fuse_kernel<<<g2, 256>>>(x, w5, w8, out);
}

// round 11
// speedup vs baseline: 2.5473x; 1.1423x over previous
#include <cuda_runtime.h>
#include <cuda_fp16.h>

#define N_ 16
#define C_ 64
#define H_ 64
#define W_ 64

// ---- static device scratch (allocation-free) ------------------------------
__device__ __align__(16) float g_t4[N_ * C_ * H_ * W_];          // 16 MB
// fp16 weights: [tap(49)][chunk(2)][co(64)][32 halves interleaved], negated
__device__ __align__(16) __half g_wt16[49 * 2 * 64 * 32];        // 401 KB

#define MMA_F16(D, a0,a1,a2,a3, b0,b1)                                        \
    asm volatile("mma.sync.aligned.m16n8k16.row.col.f32.f16.f16.f32 "         \
        "{%0,%1,%2,%3}, {%4,%5,%6,%7}, {%8,%9}, {%0,%1,%2,%3};"               \
        : "+f"(D[0]), "+f"(D[1]), "+f"(D[2]), "+f"(D[3])                      \
        : "r"(a0), "r"(a1), "r"(a2), "r"(a3), "r"(b0), "r"(b1))

// interleave position of k (0..31) inside a 32-halve row:
// step s = k/16, kk = k%16; c-block of 4: [2c,2c+1,2c+8,2c+9]; p = 8c+4s+sub
__device__ __forceinline__ int frag_pos32(int k) {
    int s  = k >> 4;
    int kk = k & 15;
    int c  = (kk & 7) >> 1;
    int sub = (kk < 8) ? (kk & 1) : (2 | (kk & 1));
    return 8 * c + 4 * s + sub;
}

// ---------------------------------------------------------------------------
// Weight transpose/negate into interleaved fp16 fragment layout.
// ---------------------------------------------------------------------------
__global__ void wtrans_kernel(const float* __restrict__ w4)
{
    int idx = blockIdx.x * 256 + threadIdx.x;
    if (idx >= 49 * 2 * 64 * 32) return;
    int k     = idx & 31;
    int co    = (idx >> 5) & 63;
    int chunk = (idx >> 11) & 1;
    int tap   = idx >> 12;
    int ci    = chunk * 32 + k;
    float v = -w4[co * 3136 + ci * 49 + tap];
    g_wt16[(size_t)((tap * 2 + chunk) * 64 + co) * 32 + frag_pos32(k)] = __float2half(v);
}

// ---------------------------------------------------------------------------
// Conv 7x7 via fp16 tensor cores (single GEMM, fp32 accum).
// Block: 256 thr, out tile co64 x (2 rows x 64 w) of one n. Grid (32, 16).
// Weights: A fragments loaded DIRECTLY from L2 (g_wt16) with LDG.128 — the
// tap loop has no barriers and no SMEM weight staging.
// SMEM: halo[8 rows][70 px][32 halves] (35.8KB) only.
// ---------------------------------------------------------------------------
#define HALO_HALVES (8 * 70 * 32)      // 17920

__global__ __launch_bounds__(256)
void conv7x7_mma_kernel(const float* __restrict__ x)
{
    __shared__ __align__(16) __half halo[HALO_HALVES];

    const int tid    = threadIdx.x;
    const int warp   = tid >> 5;
    const int lane   = tid & 31;
    const int warp_m = warp >> 1;     // 0..3 : co slice of 16
    const int warp_r = warp & 1;      // 0..1 : output row within tile
    const int g      = lane >> 2;     // 0..7
    const int c      = lane & 3;      // 0..3

    const int n  = blockIdx.y;
    const int h0 = blockIdx.x * 2;    // two output rows per block

    float d[8][4];
    #pragma unroll
    for (int j = 0; j < 8; j++)
        #pragma unroll
        for (int k = 0; k < 4; k++) d[j][k] = 0.0f;

    // per-thread A-fragment base inside a [co64][32] weight tile
    const int coA = warp_m * 16 + g;
    const __half* wA0 = g_wt16 + coA * 32 + c * 8;         // row coA
    const __half* wA1 = g_wt16 + (coA + 8) * 32 + c * 8;   // row coA+8

    for (int chunk = 0; chunk < 2; chunk++) {
        __syncthreads();   // previous chunk readers done before halo overwrite

        // ---- zero halo ----
        float4* hz = (float4*)halo;
        for (int i = tid; i < HALO_HALVES / 8; i += 256)
            hz[i] = make_float4(0.f, 0.f, 0.f, 0.f);
        __syncthreads();

        // ---- fill halo: rows h0-3 .. h0+4, interleaved fp16 ----
        for (int i = tid; i < 8 * 64 * 32; i += 256) {
            int w  = i & 63;
            int cl = (i >> 6) & 31;
            int r  = i >> 11;              // 0..7
            int gh = h0 - 3 + r;
            if ((unsigned)gh < (unsigned)H_) {
                float v = x[((n * C_ + chunk * 32 + cl) * H_ + gh) * W_ + w];
                halo[(r * 70 + w + 3) * 32 + frag_pos32(cl)] = __float2half(v);
            }
        }
        __syncthreads();   // halo visible

        #pragma unroll 1
        for (int kh = 0; kh < 7; kh++) {
            const __half* hrow = halo + ((kh + warp_r) * 70 + g) * 32 + c * 8;
            #pragma unroll
            for (int kw = 0; kw < 7; kw++) {
                const int tap = kh * 7 + kw;
                const size_t toff = (size_t)((tap * 2 + chunk) * 64) * 32;
                // A fragments straight from L2 (both k-steps in one row)
                uint4 A0 = *(const uint4*)(wA0 + toff);
                uint4 A1 = *(const uint4*)(wA1 + toff);

                const __half* hb = hrow + kw * 32;
                #pragma unroll
                for (int j = 0; j < 8; j++) {
                    uint4 B = *(const uint4*)(hb + j * (8 * 32));
                    MMA_F16(d[j], A0.x, A1.x, A0.y, A1.y, B.x, B.y);   // k-step 0
                    MMA_F16(d[j], A0.z, A1.z, A0.w, A1.w, B.z, B.w);   // k-step 1
                }
            }
        }
    }

    // ---- store t4 tile (row h0 + warp_r, full 64 px) ----
    const int hrow_o = h0 + warp_r;
    #pragma unroll
    for (int j = 0; j < 8; j++) {
        int wcol = j * 8 + 2 * c;
        #pragma unroll
        for (int s = 0; s < 2; s++) {
            int co = warp_m * 16 + g + s * 8;
            float2 v = make_float2(d[j][s * 2], d[j][s * 2 + 1]);
            *(float2*)&g_t4[((n * C_ + co) * H_ + hrow_o) * W_ + wcol] = v;
        }
    }
}

// ---------------------------------------------------------------------------
// Kernel 2 (unchanged): out = x * depthwise(t4) + w8 @ roll(x,1,H)
// ---------------------------------------------------------------------------
typedef unsigned long long ull_t;
__device__ __forceinline__ void ffma2(ull_t& d, ull_t a, ull_t b) {
    asm("fma.rn.f32x2 %0, %1, %2, %0;" : "+l"(d) : "l"(a), "l"(b));
}
__device__ __forceinline__ ull_t bcast2(float v) {
    ull_t r; asm("mov.b64 %0, {%1, %1};" : "=l"(r) : "f"(v)); return r;
}
__device__ __forceinline__ void unpack2(ull_t v, float& lo, float& hi) {
    asm("mov.b64 {%0, %1}, %2;" : "=f"(lo), "=f"(hi) : "l"(v));
}

#define SW8S 66

__global__ __launch_bounds__(256)
void fuse_kernel(const float* __restrict__ x, const float* __restrict__ w5,
                 const float* __restrict__ w8, float* __restrict__ out)
{
    __shared__ __align__(16) float sxr[64 * 64];
    __shared__ __align__(16) float sw8t[64 * SW8S];

    const int h  = blockIdx.x;
    const int n  = blockIdx.y;
    const int hr = (h + H_ - 1) & (H_ - 1);
    const int tid = threadIdx.x;

    const float* xn = x + n * (C_ * H_ * W_);

    for (int idx = tid; idx < 64 * 64; idx += 256) {
        int ci = idx >> 6, w = idx & 63;
        sxr[idx] = xn[ci * (H_ * W_) + hr * W_ + w];
    }
    for (int idx = tid; idx < 64 * 64; idx += 256) {
        int co = idx >> 6, ci = idx & 63;
        sw8t[ci * SW8S + co] = w8[co * 64 + ci];
    }
    __syncthreads();

    const int warp = tid >> 5;
    const int lane = tid & 31;
    const int co0  = warp * 8;

    ull_t acc2[4][2];
    #pragma unroll
    for (int j2 = 0; j2 < 4; j2++) { acc2[j2][0] = 0ULL; acc2[j2][1] = 0ULL; }

    #pragma unroll 4
    for (int ci = 0; ci < 64; ci++) {
        ull_t xpa = bcast2(sxr[ci * 64 + lane]);
        ull_t xpb = bcast2(sxr[ci * 64 + lane + 32]);
        const ull_t* wp = (const ull_t*)&sw8t[ci * SW8S + co0];
        #pragma unroll
        for (int j2 = 0; j2 < 4; j2++) {
            ull_t w2 = wp[j2];
            ffma2(acc2[j2][0], w2, xpa);
            ffma2(acc2[j2][1], w2, xpb);
        }
    }

    #pragma unroll
    for (int j2 = 0; j2 < 4; j2++) {
        #pragma unroll
        for (int v = 0; v < 2; v++) {
            const int w = lane + 32 * v;
            float tlo, thi;
            unpack2(acc2[j2][v], tlo, thi);
            float tacc[2] = { tlo, thi };
            #pragma unroll
            for (int s = 0; s < 2; s++) {
                const int co = co0 + 2 * j2 + s;
                const float* t4row = g_t4 + ((n * C_ + co) * H_ + h) * W_;
                const float* xrow  = xn + co * (H_ * W_) + h * W_;
                float*       orow  = out + ((size_t)((n * C_ + co) * H_ + h)) * W_;
                const float a0 = w5[co * 3 + 0];
                const float a1 = w5[co * 3 + 1];
                const float a2 = w5[co * 3 + 2];
                float tm = (w >= 2)      ? t4row[w - 2] : 0.0f;
                float tc = t4row[w];
                float tp = (w < W_ - 2)  ? t4row[w + 2] : 0.0f;
                float t5 = a0 * tm + a1 * tc + a2 * tp;
                orow[w] = xrow[w] * t5 + tacc[s];
            }
        }
    }
}

// ---------------------------------------------------------------------------
extern "C" void kernel_launch(void* const* d_in, const int* in_sizes, int n_in,
                              void* d_out, int out_size)
{
    const float* x  = (const float*)d_in[0];   // (16,64,64,64)
    const float* w4 = (const float*)d_in[1];   // (64,64,7,7)
    const float* w5 = (const float*)d_in[2];   // (64,1,1,3)
    const float* w8 = (const float*)d_in[3];   // (64,64,1,1)
    float* out = (float*)d_out;

    wtrans_kernel<<<784, 256>>>(w4);

    dim3 g1(H_ / 2, N_);             // (32, 16)
    conv7x7_mma_kernel<<<g1, 256>>>(x);

    dim3 g2(H_, N_);                 // (64, 16)
    fuse_kernel<<<g2, 256>>>(x, w5, w8, out);
}